// round 14
// baseline (speedup 1.0000x reference)
#include <cuda_runtime.h>
#include <cuda_bf16.h>
#include <cstdint>

#define NB 32
#define WPB 8
#define THREADS (WPB * 32)
#define STRIDE 36   // padded row; floats [32..35] of row j hold h[j] (overlay)

__device__ __forceinline__ float sqrt_approx(float x) {
    float r;
    asm("sqrt.approx.f32 %0, %1;" : "=f"(r) : "f"(x));   // sqrt.approx(+0)=+0
    return r;
}

__device__ __forceinline__ float fma_sat(float a, float b, float c) {
    float r;
    asm("fma.rn.sat.f32 %0, %1, %2, %3;" : "=f"(r) : "f"(a), "f"(b), "f"(c));
    return r;
}

// ---- packed f32x2 helpers (FFMA2 path, PTX-only) ----
__device__ __forceinline__ uint64_t pk2(float a, float b) {
    uint64_t r;
    asm("mov.b64 %0, {%1, %2};" : "=l"(r) : "f"(a), "f"(b));
    return r;
}
__device__ __forceinline__ void upk2(uint64_t p, float& a, float& b) {
    asm("mov.b64 {%0, %1}, %2;" : "=f"(a), "=f"(b) : "l"(p));
}
__device__ __forceinline__ uint64_t fma2(uint64_t a, uint64_t b, uint64_t c) {
    uint64_t r;
    asm("fma.rn.f32x2 %0, %1, %2, %3;" : "=l"(r) : "l"(a), "l"(b), "l"(c));
    return r;
}
__device__ __forceinline__ uint64_t mul2(uint64_t a, uint64_t b) {
    uint64_t r;
    asm("mul.rn.f32x2 %0, %1, %2;" : "=l"(r) : "l"(a), "l"(b));
    return r;
}

__device__ __forceinline__ uint64_t policy_evict_last() {
    uint64_t p;
    asm("createpolicy.fractional.L2::evict_last.b64 %0, 1.0;" : "=l"(p));
    return p;
}

__device__ __forceinline__ void cp_async16_el(float* smem_dst, const float* gmem_src,
                                              uint64_t pol) {
    unsigned sa = (unsigned)__cvta_generic_to_shared(smem_dst);
    asm volatile("cp.async.cg.shared.global.L2::cache_hint [%0], [%1], 16, %2;\n"
                 :: "r"(sa), "l"(gmem_src), "l"(pol) : "memory");
}

__device__ __forceinline__ float ldg_evict_last(const float* p, uint64_t pol) {
    float v;
    asm("ld.global.L2::cache_hint.f32 %0, [%1], %2;" : "=f"(v) : "l"(p), "l"(pol));
    return v;
}

__global__ __launch_bounds__(THREADS, 6)
void BioTokenMucusSim_kernel(const float* __restrict__ h,
                             const float* __restrict__ W,
                             const float* __restrict__ stim,
                             float* __restrict__ h_out,
                             float* __restrict__ W_out,
                             int n_pairs)
{
    // 8 warps x 32 rows x 36 floats = 36864 B/block -> 6 blocks/SM, 48 warps
    __shared__ float wsh[WPB][NB * STRIDE];

    const int warp = threadIdx.x >> 5;
    const int lane = threadIdx.x & 31;
    const int pair = blockIdx.x * WPB + warp;
    if (pair >= n_pairs) return;

    const float* Wp = W + (size_t)pair * (NB * NB);
    float* ws = wsh[warp];

    const int qr = lane >> 3;        // row-in-group
    const int qc = (lane & 7) * 4;   // float4 col offset

    const uint64_t pol = policy_evict_last();

    // ---- W tile + h: global->shared via cp.async, inputs pinned evict_last ----
    #pragma unroll
    for (int t = 0; t < 8; ++t) {
        const int r = t * 4 + qr;
        cp_async16_el(ws + r * STRIDE + qc, Wp + r * NB + qc, pol);
    }
    cp_async16_el(ws + lane * STRIDE + 32, h + (size_t)pair * NB * 4 + lane * 4, pol);
    asm volatile("cp.async.commit_group;\n" ::: "memory");

    const float s = ldg_evict_last(stim + (size_t)pair * NB + lane, pol);

    asm volatile("cp.async.wait_group 0;\n" ::: "memory");
    __syncwarp();

    // diag := 0 — serves the matvec AND makes the update's diagonal exact 0
    ws[lane * STRIDE + lane] = 0.0f;
    const float4 hv = *(const float4*)(ws + lane * STRIDE + 32);
    __syncwarp();

    // ---- masked matvec: row from shared, h via 1-wf broadcasts ----
    float ifx = 0.f, ify = 0.f, ifz = 0.f, ifw = 0.f, wsum = 0.f;
    #pragma unroll
    for (int t = 0; t < 8; ++t) {
        const float4 w4 = *(const float4*)(ws + lane * STRIDE + t * 4);
        const float wq[4] = {w4.x, w4.y, w4.z, w4.w};
        #pragma unroll
        for (int e = 0; e < 4; ++e) {
            const int j = t * 4 + e;
            const float4 hj = *(const float4*)(ws + j * STRIDE + 32);
            ifx  += wq[e] * hj.x;
            ify  += wq[e] * hj.y;
            ifz  += wq[e] * hj.z;
            ifw  += wq[e] * hj.w;
            wsum += wq[e];
        }
    }
    const float inv = 1.0f / (wsum + 1e-8f);
    const float En = ifx * inv, Pn = ify * inv, Gn = ifz * inv, Ln = ifw * inv;

    // ---- channel update (.sat replaces clamp01) ----
    const float E = hv.x, P = hv.y, G = hv.z, L = hv.w;
    const float E_new = fma_sat(-0.2f, G, fmaf(-0.4f, P, fmaf(0.3f, s, E)));
    const float P_new = fma_sat(-0.2f, E, fmaf(0.3f, Pn - P, fmaf(0.5f, s, P)));
    const float G_new = fma_sat(-0.3f, P, fmaf(0.2f, Gn - G,
                                fmaf(0.4f * E, 1.0f - P, G)));
    const float good  = 0.5f * En + 0.5f * Gn;
    const float L_new = fma_sat(-0.3f, P, fmaf(0.3f, Ln - L, fmaf(0.4f, good, L)));

    const float4 hn = make_float4(E_new, P_new, G_new, L_new);
    __stcs((float4*)(h_out + (size_t)pair * NB * 4) + lane, hn);   // streaming store

    __syncwarp();                                  // matvec h reads done
    *(float4*)(ws + lane * STRIDE + 32) = hn;      // publish h_new
    __syncwarp();

    // ---- fused W-update + streaming store (f32x2-packed dist; .sat clamp) ----
    // diag is implicit 0: wq[diag]=0 (zeroed in shared) and dist(diag)=sqrt(0)=0
    const uint64_t NEG1 = pk2(-1.0f, -1.0f);
    const uint64_t C95  = pk2(0.95f, 0.95f);

    uint64_t hjxy[4], hjzw[4];
    float lj05[4];
    #pragma unroll
    for (int e = 0; e < 4; ++e) {
        const float4 v = *(const float4*)(ws + (qc + e) * STRIDE + 32);
        hjxy[e] = pk2(v.x, v.y);
        hjzw[e] = pk2(v.z, v.w);
        lj05[e] = 0.05f * v.w;
    }

    float* Wo = W_out + (size_t)pair * (NB * NB);
    #pragma unroll
    for (int t = 0; t < 8; ++t) {
        const int r = t * 4 + qr;
        const float4 w  = *(const float4*)(ws + r * STRIDE + qc);
        const float4 hr = *(const float4*)(ws + r * STRIDE + 32);
        const uint64_t hrxy = pk2(hr.x, hr.y);
        const uint64_t hrzw = pk2(hr.z, hr.w);
        const float hr05 = 0.05f * hr.w;

        float wm[4];
        {
            const uint64_t wm01 = mul2(pk2(w.x, w.y), C95);
            const uint64_t wm23 = mul2(pk2(w.z, w.w), C95);
            upk2(wm01, wm[0], wm[1]);
            upk2(wm23, wm[2], wm[3]);
        }

        float out[4];
        #pragma unroll
        for (int e = 0; e < 4; ++e) {
            const uint64_t dxy = fma2(hjxy[e], NEG1, hrxy);   // hr - hj (exact)
            const uint64_t dzw = fma2(hjzw[e], NEG1, hrzw);
            uint64_t s2 = mul2(dxy, dxy);
            s2 = fma2(dzw, dzw, s2);
            float f0, f1;
            upk2(s2, f0, f1);
            const float dist = sqrt_approx(f0 + f1);
            out[e] = fma_sat(hr05 + lj05[e], dist, wm[e]);
        }
        __stcs((float4*)(Wo + r * NB) + (lane & 7),
               make_float4(out[0], out[1], out[2], out[3]));
    }
}

extern "C" void kernel_launch(void* const* d_in, const int* in_sizes, int n_in,
                              void* d_out, int out_size) {
    const float* h    = (const float*)d_in[0];  // [B,S,32,4]
    const float* W    = (const float*)d_in[1];  // [B,S,32,32]
    const float* stim = (const float*)d_in[2];  // [B,S,32]

    const int n_pairs = in_sizes[2] / NB;       // B*S = 16384

    float* h_out = (float*)d_out;                       // h_new first
    float* W_out = (float*)d_out + (size_t)in_sizes[0]; // then W_new

    const int blocks = (n_pairs + WPB - 1) / WPB;       // 2048
    BioTokenMucusSim_kernel<<<blocks, THREADS>>>(h, W, stim, h_out, W_out, n_pairs);
}